// round 3
// baseline (speedup 1.0000x reference)
#include <cuda_runtime.h>
#include <math.h>

// ---------------------------------------------------------------------------
// Problem constants
// ---------------------------------------------------------------------------
#define B_    16
#define T_    64
#define HW_   512
#define E_    256
#define E2_   512
#define V_    128
#define BT_   1024   // B*T
#define NBLK_ 3

typedef unsigned long long ull;

// ---------------------------------------------------------------------------
// Scratch (device globals: no allocation allowed)
// ---------------------------------------------------------------------------
__device__ __align__(16) float g_s  [BT_ * E_];      // embed(labels), fixed
__device__ __align__(16) float g_a  [BT_ * E_];      // running activation
__device__ __align__(16) float g_z  [BT_ * E_];      // GLU output
__device__ __align__(16) float g_h  [BT_ * E_];      // query
__device__ __align__(16) float g_res[B_ * HW_ * E_]; // enc + dec
__device__ __align__(16) float g_Wt [E_ * E_];       // W_w transposed: Wt[i][o]
__device__ __align__(16) float g_Wop[E_ * V_];       // Wo interleaved e-pairs

// ---------------------------------------------------------------------------
// f32x2 packed math (sm_100+)
// ---------------------------------------------------------------------------
__device__ __forceinline__ ull pack2(float x, float y) {
    ull r; asm("mov.b64 %0, {%1,%2};" : "=l"(r) : "f"(x), "f"(y)); return r;
}
__device__ __forceinline__ void unpack2(ull v, float& x, float& y) {
    asm("mov.b64 {%0,%1}, %2;" : "=f"(x), "=f"(y) : "l"(v));
}
__device__ __forceinline__ ull ffma2(ull a, ull b, ull c) {
    ull d; asm("fma.rn.f32x2 %0, %1, %2, %3;" : "=l"(d) : "l"(a), "l"(b), "l"(c)); return d;
}
__device__ __forceinline__ ull fmul2(ull a, ull b) {
    ull d; asm("mul.rn.f32x2 %0, %1, %2;" : "=l"(d) : "l"(a), "l"(b)); return d;
}
__device__ __forceinline__ ull fadd2(ull a, ull b) {
    ull d; asm("add.rn.f32x2 %0, %1, %2;" : "=l"(d) : "l"(a), "l"(b)); return d;
}

// ---------------------------------------------------------------------------
// K1: s = embed[labels]; a = s
// ---------------------------------------------------------------------------
__global__ __launch_bounds__(256) void k_embed(const int* __restrict__ labels,
                                               const float* __restrict__ emb) {
    int row = blockIdx.x;                 // 0..1023 == b*T + t
    int e   = threadIdx.x;
    int lbl = labels[row];
    float v = emb[lbl * E_ + e];
    g_s[row * E_ + e] = v;
    g_a[row * E_ + e] = v;
}

// ---------------------------------------------------------------------------
// K2: residual = enc + dec (flat elementwise, float4)
// ---------------------------------------------------------------------------
__global__ __launch_bounds__(256) void k_residual(const float* __restrict__ enc,
                                                  const float* __restrict__ dec) {
    int i = blockIdx.x * blockDim.x + threadIdx.x;   // float4 index
    float4 a = ((const float4*)enc)[i];
    float4 b = ((const float4*)dec)[i];
    float4 c;
    c.x = a.x + b.x; c.y = a.y + b.y; c.z = a.z + b.z; c.w = a.w + b.w;
    ((float4*)g_res)[i] = c;
}

// ---------------------------------------------------------------------------
// K3: weight prep — transpose W_w; interleave Wo into e-pair layout
//   g_Wt[i*E + o]                    = W_w[o*E + i]
//   g_Wop[(e>>1)*2V + 2v + (e&1)]    = Wo_w[v*E + e]
// ---------------------------------------------------------------------------
__global__ __launch_bounds__(256) void k_prep(const float* __restrict__ Ww,
                                              const float* __restrict__ Wo) {
    if (blockIdx.x < E_) {
        int o = blockIdx.x, i = threadIdx.x;
        g_Wt[i * E_ + o] = Ww[o * E_ + i];
    } else {
        int v = blockIdx.x - E_;          // 0..127
        int e = threadIdx.x;              // 0..255
        g_Wop[(e >> 1) * (2 * V_) + 2 * v + (e & 1)] = Wo[v * E_ + e];
    }
}

// ---------------------------------------------------------------------------
// K4: conv (K=3, pad 1) + bias + GLU   -> g_z
// grid 128 = B * (T/8); 256 threads; thread = cout pair (co, co+256) packed
// ---------------------------------------------------------------------------
__global__ __launch_bounds__(256) void k_convglu(const float* __restrict__ w,
                                                 const float* __restrict__ bias) {
    __shared__ __align__(16) float as[10][E_];       // rows t0-1 .. t0+8
    int b  = blockIdx.x >> 3;
    int t0 = (blockIdx.x & 7) << 3;
    int co = threadIdx.x;

    #pragma unroll
    for (int r = 0; r < 10; ++r) {
        int t = t0 - 1 + r;
        as[r][co] = (t >= 0 && t < T_) ? g_a[(b * T_ + t) * E_ + co] : 0.f;
    }
    __syncthreads();

    ull acc[8];
    ull binit = pack2(bias[co], bias[co + E_]);
    #pragma unroll
    for (int tt = 0; tt < 8; ++tt) acc[tt] = binit;

    for (int ci = 0; ci < E_; ++ci) {
        ull xp[10];
        #pragma unroll
        for (int r = 0; r < 10; ++r) { float xv = as[r][ci]; xp[r] = pack2(xv, xv); }
        #pragma unroll
        for (int k = 0; k < 3; ++k) {
            const float* wr = w + (k * E_ + ci) * E2_;
            ull wp = pack2(wr[co], wr[co + E_]);
            #pragma unroll
            for (int tt = 0; tt < 8; ++tt)
                acc[tt] = ffma2(xp[tt + k], wp, acc[tt]);
        }
    }

    #pragma unroll
    for (int tt = 0; tt < 8; ++tt) {
        float za, zb; unpack2(acc[tt], za, zb);
        float zz = za / (1.f + expf(-zb));           // GLU
        g_z[(b * T_ + t0 + tt) * E_ + co] = zz;
    }
}

// ---------------------------------------------------------------------------
// K5: h = z @ W_w^T + W_b + s   -> g_h
// grid 128 (8 rows each); 256 threads; thread = output channel o
// ---------------------------------------------------------------------------
__global__ __launch_bounds__(256) void k_hW(const float* __restrict__ Wb) {
    __shared__ __align__(16) float zt[E_][10];       // transposed z tile (pad 10)
    int row0 = blockIdx.x * 8;
    int o    = threadIdx.x;

    #pragma unroll
    for (int r = 0; r < 8; ++r) zt[o][r] = g_z[(row0 + r) * E_ + o];
    __syncthreads();

    ull acc[4];
    #pragma unroll
    for (int p = 0; p < 4; ++p) acc[p] = pack2(0.f, 0.f);

    for (int i = 0; i < E_; ++i) {
        float wv = g_Wt[i * E_ + o];                 // coalesced
        ull wp = pack2(wv, wv);
        const ull* zp = (const ull*)&zt[i][0];       // row pairs, broadcast LDS
        #pragma unroll
        for (int p = 0; p < 4; ++p) acc[p] = ffma2(zp[p], wp, acc[p]);
    }

    float wb = Wb[o];
    #pragma unroll
    for (int p = 0; p < 4; ++p) {
        float h0, h1; unpack2(acc[p], h0, h1);
        int r = 2 * p;
        g_h[(row0 + r)     * E_ + o] = h0 + wb + g_s[(row0 + r)     * E_ + o];
        g_h[(row0 + r + 1) * E_ + o] = h1 + wb + g_s[(row0 + r + 1) * E_ + o];
    }
}

// ---------------------------------------------------------------------------
// K6: attention: scores = h @ dec^T, softmax over HW, c = alpha @ res,
//     a_new = c + z
// grid 128 = B * (T/8); 256 threads
// ---------------------------------------------------------------------------
__global__ __launch_bounds__(256) void k_attn(const float* __restrict__ dec) {
    __shared__ __align__(16) float qs [8][E_];       // 8 KB
    __shared__ __align__(16) float sst[HW_][10];     // 20 KB: [s][t] pad 10
    __shared__ float rsum[8];

    int b    = blockIdx.x >> 3;
    int t0   = (blockIdx.x & 7) << 3;
    int tid  = threadIdx.x;
    int lane = tid & 31;
    int wid  = tid >> 5;

    #pragma unroll
    for (int r = 0; r < 8; ++r)
        qs[r][tid] = g_h[(b * T_ + t0 + r) * E_ + tid];
    __syncthreads();

    // ---- phase 1: raw scores (warp owns 64 keys; lane owns 8 e's) ----
    const float* decb = dec + (size_t)b * HW_ * E_;
    for (int s = wid * 64; s < wid * 64 + 64; ++s) {
        const ulonglong2* kp = (const ulonglong2*)(decb + s * E_ + lane * 8);
        ulonglong2 kA = kp[0], kB = kp[1];
        #pragma unroll
        for (int t = 0; t < 8; ++t) {
            const ulonglong2* qp = (const ulonglong2*)&qs[t][lane * 8];
            ulonglong2 qA = qp[0], qB = qp[1];
            ull acc = fmul2(qA.x, kA.x);
            acc = ffma2(qA.y, kA.y, acc);
            acc = ffma2(qB.x, kB.x, acc);
            acc = ffma2(qB.y, kB.y, acc);
            #pragma unroll
            for (int off = 16; off; off >>= 1)
                acc = fadd2(acc, __shfl_xor_sync(0xffffffffu, acc, off));
            if (lane == 0) {
                float lo, hi; unpack2(acc, lo, hi);
                sst[s][t] = lo + hi;
            }
        }
    }
    __syncthreads();

    // ---- phase 2: softmax over s (warp wid handles t = wid) ----
    {
        int t = wid;
        float m = -1e30f;
        for (int s = lane; s < HW_; s += 32) m = fmaxf(m, sst[s][t]);
        #pragma unroll
        for (int off = 16; off; off >>= 1)
            m = fmaxf(m, __shfl_xor_sync(0xffffffffu, m, off));
        float sum = 0.f;
        for (int s = lane; s < HW_; s += 32) {
            float ev = expf(sst[s][t] - m);
            sst[s][t] = ev;
            sum += ev;
        }
        #pragma unroll
        for (int off = 16; off; off >>= 1)
            sum += __shfl_xor_sync(0xffffffffu, sum, off);
        if (lane == 0) rsum[t] = 1.f / sum;
    }
    __syncthreads();

    // ---- phase 3: c = (exp-scores @ res) * rsum; a = c + z ----
    const float* resb = g_res + (size_t)b * HW_ * E_;
    int e = tid;
    ull acc[4];
    #pragma unroll
    for (int p = 0; p < 4; ++p) acc[p] = pack2(0.f, 0.f);

    for (int s = 0; s < HW_; ++s) {
        float rv = resb[s * E_ + e];                 // coalesced
        ull rp = pack2(rv, rv);
        const ull* ap = (const ull*)&sst[s][0];      // t-pairs, broadcast LDS
        #pragma unroll
        for (int p = 0; p < 4; ++p) acc[p] = ffma2(ap[p], rp, acc[p]);
    }

    #pragma unroll
    for (int p = 0; p < 4; ++p) {
        float c0, c1; unpack2(acc[p], c0, c1);
        int t = 2 * p;
        int idx = (b * T_ + t0 + t) * E_ + e;
        g_a[idx]      = c0 * rsum[t]     + g_z[idx];
        g_a[idx + E_] = c1 * rsum[t + 1] + g_z[idx + E_];
    }
}

// ---------------------------------------------------------------------------
// K7: logits = a @ Wo^T + Wo_b; log_softmax over V  -> out
// grid 256 (4 rows each); 128 threads; thread = vocab v
// ---------------------------------------------------------------------------
__global__ __launch_bounds__(128) void k_logits(const float* __restrict__ Wob,
                                                float* __restrict__ out) {
    __shared__ __align__(16) float av4[4][E_];
    __shared__ float redm[4][4], reds[4][4];

    int row0 = blockIdx.x * 4;
    int v    = threadIdx.x;
    int lane = v & 31;
    int wid  = v >> 5;

    #pragma unroll
    for (int r = 0; r < 4; ++r) {
        av4[r][v]       = g_a[(row0 + r) * E_ + v];
        av4[r][v + 128] = g_a[(row0 + r) * E_ + v + 128];
    }
    __syncthreads();

    ull acc[4];
    #pragma unroll
    for (int r = 0; r < 4; ++r) acc[r] = pack2(0.f, 0.f);

    const ull* wop = (const ull*)g_Wop;
    #pragma unroll 4
    for (int ep = 0; ep < E_ / 2; ++ep) {
        ull wp = wop[ep * V_ + v];                   // coalesced LDG.64
        #pragma unroll
        for (int r = 0; r < 4; ++r)
            acc[r] = ffma2(((const ull*)av4[r])[ep], wp, acc[r]);
    }

    float lg[4], wb = Wob[v];
    #pragma unroll
    for (int r = 0; r < 4; ++r) {
        float lo, hi; unpack2(acc[r], lo, hi);
        lg[r] = lo + hi + wb;
    }

    // block-wide max per row
    float wm[4];
    #pragma unroll
    for (int r = 0; r < 4; ++r) {
        wm[r] = lg[r];
        #pragma unroll
        for (int off = 16; off; off >>= 1)
            wm[r] = fmaxf(wm[r], __shfl_xor_sync(0xffffffffu, wm[r], off));
    }
    if (lane == 0) {
        #pragma unroll
        for (int r = 0; r < 4; ++r) redm[r][wid] = wm[r];
    }
    __syncthreads();
    float bm[4];
    #pragma unroll
    for (int r = 0; r < 4; ++r)
        bm[r] = fmaxf(fmaxf(redm[r][0], redm[r][1]), fmaxf(redm[r][2], redm[r][3]));

    // block-wide sum(exp) per row
    float ws[4];
    #pragma unroll
    for (int r = 0; r < 4; ++r) {
        ws[r] = expf(lg[r] - bm[r]);
        #pragma unroll
        for (int off = 16; off; off >>= 1)
            ws[r] += __shfl_xor_sync(0xffffffffu, ws[r], off);
    }
    if (lane == 0) {
        #pragma unroll
        for (int r = 0; r < 4; ++r) reds[r][wid] = ws[r];
    }
    __syncthreads();

    #pragma unroll
    for (int r = 0; r < 4; ++r) {
        float bs = reds[r][0] + reds[r][1] + reds[r][2] + reds[r][3];
        out[(row0 + r) * V_ + v] = lg[r] - bm[r] - logf(bs);
    }
}

// ---------------------------------------------------------------------------
// kernel_launch
// ---------------------------------------------------------------------------
extern "C" void kernel_launch(void* const* d_in, const int* in_sizes, int n_in,
                              void* d_out, int out_size) {
    // Locate labels (unique element count 1024) to disambiguate input ordering.
    int li = 2;
    for (int i = 0; i < n_in; ++i)
        if (in_sizes[i] == 1024) { li = i; break; }

    const float *enc, *dec, *emb, *cw, *cb, *Ww, *Wb, *Wo, *Wob;
    const int* labels;
    if (li == 2) {
        // setup_inputs dict order
        enc = (const float*)d_in[0]; dec = (const float*)d_in[1];
        labels = (const int*)d_in[2];
        emb = (const float*)d_in[3]; cw  = (const float*)d_in[4];
        cb  = (const float*)d_in[5]; Ww  = (const float*)d_in[6];
        Wb  = (const float*)d_in[7]; Wo  = (const float*)d_in[8];
        Wob = (const float*)d_in[9];
    } else {
        // reference() signature order (labels last)
        enc = (const float*)d_in[0]; dec = (const float*)d_in[1];
        emb = (const float*)d_in[2]; cw  = (const float*)d_in[3];
        cb  = (const float*)d_in[4]; Ww  = (const float*)d_in[5];
        Wb  = (const float*)d_in[6]; Wo  = (const float*)d_in[7];
        Wob = (const float*)d_in[8];
        labels = (const int*)d_in[9];
    }
    float* out = (float*)d_out;

    k_embed   <<<BT_, 256>>>(labels, emb);
    k_residual<<<(B_ * HW_ * E_) / 4 / 256, 256>>>(enc, dec);
    k_prep    <<<E_ + V_, 256>>>(Ww, Wo);

    for (int l = 0; l < NBLK_; ++l) {
        k_convglu<<<128, 256>>>(cw, cb);
        k_hW     <<<128, 256>>>(Wb);
        k_attn   <<<128, 256>>>(dec);
    }

    k_logits<<<BT_ / 4, 128>>>(Wob, out);
}

// round 4
// speedup vs baseline: 1.4363x; 1.4363x over previous
#include <cuda_runtime.h>
#include <math.h>

// ---------------------------------------------------------------------------
// Problem constants
// ---------------------------------------------------------------------------
#define B_    16
#define T_    64
#define HW_   512
#define E_    256
#define E2_   512
#define V_    128
#define BT_   1024   // B*T
#define NBLK_ 3

typedef unsigned long long ull;

// ---------------------------------------------------------------------------
// Scratch (device globals: no allocation allowed)
// ---------------------------------------------------------------------------
__device__ __align__(16) float g_s   [BT_ * E_];       // embed(labels), fixed
__device__ __align__(16) float g_a   [BT_ * E_];       // running activation
__device__ __align__(16) float g_z   [BT_ * E_];       // GLU output
__device__ __align__(16) float g_h   [BT_ * E_];       // query
__device__ __align__(16) float g_res [B_ * HW_ * E_];  // enc + dec
__device__ __align__(16) float g_Wt  [E_ * E_];        // W_w transposed: Wt[i][o]
__device__ __align__(16) float g_Wop [E_ * V_];        // Wo interleaved e-pairs
__device__ __align__(16) float g_cw2 [3 * E_ * E2_];   // conv_w, GLU-interleaved cols
__device__ __align__(16) float g_cb2 [E2_];            // conv_b, interleaved
__device__ __align__(16) float g_decT[B_ * E_ * HW_];  // dec transposed [b][e][s]

// ---------------------------------------------------------------------------
// f32x2 packed math (sm_100+)
// ---------------------------------------------------------------------------
__device__ __forceinline__ ull pack2(float x, float y) {
    ull r; asm("mov.b64 %0, {%1,%2};" : "=l"(r) : "f"(x), "f"(y)); return r;
}
__device__ __forceinline__ void unpack2(ull v, float& x, float& y) {
    asm("mov.b64 {%0,%1}, %2;" : "=f"(x), "=f"(y) : "l"(v));
}
__device__ __forceinline__ ull ffma2(ull a, ull b, ull c) {
    ull d; asm("fma.rn.f32x2 %0, %1, %2, %3;" : "=l"(d) : "l"(a), "l"(b), "l"(c)); return d;
}

// ---------------------------------------------------------------------------
// K1: s = embed[labels]; a = s
// ---------------------------------------------------------------------------
__global__ __launch_bounds__(256) void k_embed(const int* __restrict__ labels,
                                               const float* __restrict__ emb) {
    int row = blockIdx.x;
    int e   = threadIdx.x;
    int lbl = labels[row];
    float v = emb[lbl * E_ + e];
    g_s[row * E_ + e] = v;
    g_a[row * E_ + e] = v;
}

// ---------------------------------------------------------------------------
// K2: residual = enc + dec (flat elementwise, float4)
// ---------------------------------------------------------------------------
__global__ __launch_bounds__(256) void k_residual(const float* __restrict__ enc,
                                                  const float* __restrict__ dec) {
    int i = blockIdx.x * blockDim.x + threadIdx.x;
    float4 a = ((const float4*)enc)[i];
    float4 b = ((const float4*)dec)[i];
    float4 c;
    c.x = a.x + b.x; c.y = a.y + b.y; c.z = a.z + b.z; c.w = a.w + b.w;
    ((float4*)g_res)[i] = c;
}

// ---------------------------------------------------------------------------
// K3: weight prep
//   g_Wt [i*E + o]               = W_w[o*E + i]
//   g_Wop[(e>>1)*2V + 2v+(e&1)]  = Wo_w[v*E + e]
//   g_cw2[kk*512 + 2j+p]         = conv_w[kk*512 + p*256 + j]   (GLU pairing)
//   g_cb2[2j+p]                  = conv_b[p*256 + j]
// ---------------------------------------------------------------------------
__global__ __launch_bounds__(256) void k_prep(const float* __restrict__ Ww,
                                              const float* __restrict__ Wo,
                                              const float* __restrict__ cw,
                                              const float* __restrict__ cb) {
    int bid = blockIdx.x, tid = threadIdx.x;
    if (bid < E_) {
        g_Wt[tid * E_ + bid] = Ww[bid * E_ + tid];
    } else if (bid < E_ + V_) {
        int v = bid - E_;
        g_Wop[(tid >> 1) * (2 * V_) + 2 * v + (tid & 1)] = Wo[v * E_ + tid];
    } else if (bid < E_ + V_ + 3 * E_) {
        int kk = bid - (E_ + V_);
        #pragma unroll
        for (int h = 0; h < 2; ++h) {
            int c = tid + h * 256;
            int j = c >> 1, p = c & 1;
            g_cw2[kk * E2_ + c] = cw[kk * E2_ + p * E_ + j];
        }
    } else {
        #pragma unroll
        for (int h = 0; h < 2; ++h) {
            int c = tid + h * 256;
            int j = c >> 1, p = c & 1;
            g_cb2[c] = cb[p * E_ + j];
        }
    }
}

// ---------------------------------------------------------------------------
// K3b: transpose dec -> g_decT[b][e][s]
// ---------------------------------------------------------------------------
__global__ void k_transpose(const float* __restrict__ dec) {
    __shared__ float tile[32][33];
    int b  = blockIdx.z;
    int s0 = blockIdx.x << 5;
    int e0 = blockIdx.y << 5;
    int tx = threadIdx.x, ty = threadIdx.y;
    #pragma unroll
    for (int i = 0; i < 32; i += 8)
        tile[ty + i][tx] = dec[((b << 9) + s0 + ty + i) * E_ + e0 + tx];
    __syncthreads();
    #pragma unroll
    for (int i = 0; i < 32; i += 8)
        g_decT[((b << 8) + e0 + ty + i) * HW_ + s0 + tx] = tile[tx][ty + i];
}

// ---------------------------------------------------------------------------
// K4: conv (K=3, pad 1) + bias + GLU   -> g_z
// GEMM form: C[m=64][n=64] += A[m][kk] * B[kk][n], kk in [0,768)
//   A[m][kk] = a[bb, m + kk/256 - 1, kk%256] (zero pad)
//   B        = g_cw2 (GLU-interleaved)
// grid 128 = 16 b * 8 n-tiles; 256 threads; thread = 4m x 4n register tile
// ---------------------------------------------------------------------------
__global__ __launch_bounds__(256) void k_conv2() {
    __shared__ __align__(16) float As[2][16][68];
    __shared__ __align__(16) float Bs[2][16][68];

    int bb  = blockIdx.x >> 3;
    int n0  = (blockIdx.x & 7) << 6;
    int tid = threadIdx.x;
    int kcA = tid & 15, mm = tid >> 4;       // A loader mapping
    int kcB = tid >> 6, nn = tid & 63;       // B loader mapping
    int mi  = tid >> 4, ni = tid & 15;       // compute mapping

    const float* abase = g_a + (bb << 6) * E_;

    // prologue: chunk 0 (k=0, ci0=0)
    #pragma unroll
    for (int it = 0; it < 4; ++it) {
        int m = mm + (it << 4);
        int ts = m - 1;                       // k=0
        As[0][kcA][m] = (ts >= 0) ? abase[ts * E_ + kcA] : 0.f;
    }
    #pragma unroll
    for (int it = 0; it < 4; ++it) {
        int kc = kcB + (it << 2);
        Bs[0][kc][nn] = g_cw2[kc * E2_ + n0 + nn];
    }
    __syncthreads();

    ull acc[2][4];
    #pragma unroll
    for (int j = 0; j < 4; ++j) {
        float bj = g_cb2[n0 + ni * 4 + j];
        ull bp = pack2(bj, bj);
        acc[0][j] = bp; acc[1][j] = bp;
    }

    float aN[4], bN[4];
    for (int ch = 0; ch < 48; ++ch) {
        int cur = ch & 1;
        if (ch < 47) {
            int chn = ch + 1;
            int k   = chn >> 4;
            int ci0 = (chn & 15) << 4;
            #pragma unroll
            for (int it = 0; it < 4; ++it) {
                int m  = mm + (it << 4);
                int ts = m + k - 1;
                aN[it] = (ts >= 0 && ts < 64) ? abase[ts * E_ + ci0 + kcA] : 0.f;
            }
            #pragma unroll
            for (int it = 0; it < 4; ++it)
                bN[it] = g_cw2[((chn << 4) + kcB + (it << 2)) * E2_ + n0 + nn];
        }

        #pragma unroll
        for (int kc = 0; kc < 16; ++kc) {
            ulonglong2 av = *(const ulonglong2*)&As[cur][kc][mi * 4];
            float4     bv = *(const float4*)    &Bs[cur][kc][ni * 4];
            ull b0 = pack2(bv.x, bv.x);
            ull b1 = pack2(bv.y, bv.y);
            ull b2 = pack2(bv.z, bv.z);
            ull b3 = pack2(bv.w, bv.w);
            acc[0][0] = ffma2(av.x, b0, acc[0][0]);
            acc[0][1] = ffma2(av.x, b1, acc[0][1]);
            acc[0][2] = ffma2(av.x, b2, acc[0][2]);
            acc[0][3] = ffma2(av.x, b3, acc[0][3]);
            acc[1][0] = ffma2(av.y, b0, acc[1][0]);
            acc[1][1] = ffma2(av.y, b1, acc[1][1]);
            acc[1][2] = ffma2(av.y, b2, acc[1][2]);
            acc[1][3] = ffma2(av.y, b3, acc[1][3]);
        }

        if (ch < 47) {
            int nxt = cur ^ 1;
            #pragma unroll
            for (int it = 0; it < 4; ++it)
                As[nxt][kcA][mm + (it << 4)] = aN[it];
            #pragma unroll
            for (int it = 0; it < 4; ++it)
                Bs[nxt][kcB + (it << 2)][nn] = bN[it];
        }
        __syncthreads();
    }

    // epilogue: bias already in acc; GLU pairs are (col even=za, col odd=zb)
    int zj = (n0 >> 1) + (ni << 1);
    #pragma unroll
    for (int p = 0; p < 2; ++p) {
        float a0l, a0h, b0l, b0h, a1l, a1h, b1l, b1h;
        unpack2(acc[p][0], a0l, a0h);
        unpack2(acc[p][1], b0l, b0h);
        unpack2(acc[p][2], a1l, a1h);
        unpack2(acc[p][3], b1l, b1h);
        int m0 = mi * 4 + 2 * p;
        float* zr0 = g_z + ((bb << 6) + m0) * E_ + zj;
        float* zr1 = zr0 + E_;
        zr0[0] = a0l / (1.f + expf(-b0l));
        zr0[1] = a1l / (1.f + expf(-b1l));
        zr1[0] = a0h / (1.f + expf(-b0h));
        zr1[1] = a1h / (1.f + expf(-b1h));
    }
}

// ---------------------------------------------------------------------------
// K5: h = z @ W_w^T + W_b + s   -> g_h
// ---------------------------------------------------------------------------
__global__ __launch_bounds__(256) void k_hW(const float* __restrict__ Wb) {
    __shared__ __align__(16) float zt[E_][10];
    int row0 = blockIdx.x * 8;
    int o    = threadIdx.x;

    #pragma unroll
    for (int r = 0; r < 8; ++r) zt[o][r] = g_z[(row0 + r) * E_ + o];
    __syncthreads();

    ull acc[4];
    #pragma unroll
    for (int p = 0; p < 4; ++p) acc[p] = pack2(0.f, 0.f);

    #pragma unroll 8
    for (int i = 0; i < E_; ++i) {
        float wv = g_Wt[i * E_ + o];
        ull wp = pack2(wv, wv);
        const ull* zp = (const ull*)&zt[i][0];
        #pragma unroll
        for (int p = 0; p < 4; ++p) acc[p] = ffma2(zp[p], wp, acc[p]);
    }

    float wb = Wb[o];
    #pragma unroll
    for (int p = 0; p < 4; ++p) {
        float h0, h1; unpack2(acc[p], h0, h1);
        int r = 2 * p;
        g_h[(row0 + r)     * E_ + o] = h0 + wb + g_s[(row0 + r)     * E_ + o];
        g_h[(row0 + r + 1) * E_ + o] = h1 + wb + g_s[(row0 + r + 1) * E_ + o];
    }
}

// ---------------------------------------------------------------------------
// K6: attention. grid 128 = 16 b * 8 t-tiles; 256 threads.
// phase 1 uses g_decT (coalesced keys, no shuffle reductions):
//   thread owns s = tid and s+256, accumulates 8 t's as 4 f32x2 pairs.
// ---------------------------------------------------------------------------
__global__ __launch_bounds__(256) void k_attn() {
    __shared__ __align__(16) float qt [E_][8];      // q transposed: [e][t]
    __shared__ __align__(16) float sst[HW_][8];     // scores [s][t]
    __shared__ float rsum[8];

    int b    = blockIdx.x >> 3;
    int t0   = (blockIdx.x & 7) << 3;
    int tid  = threadIdx.x;
    int lane = tid & 31;
    int wid  = tid >> 5;
    int row0 = (b << 6) + t0;

    #pragma unroll
    for (int r = 0; r < 8; ++r)
        qt[tid][r] = g_h[(row0 + r) * E_ + tid];
    __syncthreads();

    // ---- phase 1: scores = h @ decT ----
    ull A0[4], A1[4];
    #pragma unroll
    for (int j = 0; j < 4; ++j) { A0[j] = pack2(0.f, 0.f); A1[j] = pack2(0.f, 0.f); }

    const float* kb = g_decT + ((size_t)b << 8) * HW_ + tid;
    #pragma unroll 4
    for (int e = 0; e < E_; ++e) {
        float k0 = kb[e * HW_];
        float k1 = kb[e * HW_ + 256];
        ull kp0 = pack2(k0, k0);
        ull kp1 = pack2(k1, k1);
        const ull* qp = (const ull*)&qt[e][0];
        #pragma unroll
        for (int j = 0; j < 4; ++j) {
            A0[j] = ffma2(qp[j], kp0, A0[j]);
            A1[j] = ffma2(qp[j], kp1, A1[j]);
        }
    }
    {
        ull* s0p = (ull*)&sst[tid][0];
        ull* s1p = (ull*)&sst[tid + 256][0];
        #pragma unroll
        for (int j = 0; j < 4; ++j) { s0p[j] = A0[j]; s1p[j] = A1[j]; }
    }
    __syncthreads();

    // ---- phase 2: softmax over s (warp wid handles t = wid) ----
    {
        int t = wid;
        float m = -1e30f;
        for (int s = lane; s < HW_; s += 32) m = fmaxf(m, sst[s][t]);
        #pragma unroll
        for (int off = 16; off; off >>= 1)
            m = fmaxf(m, __shfl_xor_sync(0xffffffffu, m, off));
        float sum = 0.f;
        for (int s = lane; s < HW_; s += 32) {
            float ev = expf(sst[s][t] - m);
            sst[s][t] = ev;
            sum += ev;
        }
        #pragma unroll
        for (int off = 16; off; off >>= 1)
            sum += __shfl_xor_sync(0xffffffffu, sum, off);
        if (lane == 0) rsum[t] = 1.f / sum;
    }
    __syncthreads();

    // ---- phase 3: c = (exp-scores @ res) * rsum; a = c + z ----
    const float* resb = g_res + ((size_t)b * HW_) * E_;
    int e = tid;
    ull acc[4];
    #pragma unroll
    for (int p = 0; p < 4; ++p) acc[p] = pack2(0.f, 0.f);

    #pragma unroll 4
    for (int s = 0; s < HW_; ++s) {
        float rv = resb[s * E_ + e];
        ull rp = pack2(rv, rv);
        const ull* ap = (const ull*)&sst[s][0];
        #pragma unroll
        for (int p = 0; p < 4; ++p) acc[p] = ffma2(ap[p], rp, acc[p]);
    }

    #pragma unroll
    for (int p = 0; p < 2 * 2; ++p) {
        float c0, c1; unpack2(acc[p], c0, c1);
        int t = 2 * p;
        int idx = (row0 + t) * E_ + e;
        g_a[idx]      = c0 * rsum[t]     + g_z[idx];
        g_a[idx + E_] = c1 * rsum[t + 1] + g_z[idx + E_];
    }
}

// ---------------------------------------------------------------------------
// K7: logits = a @ Wo^T + Wo_b; log_softmax over V  -> out
// ---------------------------------------------------------------------------
__global__ __launch_bounds__(128) void k_logits(const float* __restrict__ Wob,
                                                float* __restrict__ out) {
    __shared__ __align__(16) float av4[4][E_];
    __shared__ float redm[4][4], reds[4][4];

    int row0 = blockIdx.x * 4;
    int v    = threadIdx.x;
    int lane = v & 31;
    int wid  = v >> 5;

    #pragma unroll
    for (int r = 0; r < 4; ++r) {
        av4[r][v]       = g_a[(row0 + r) * E_ + v];
        av4[r][v + 128] = g_a[(row0 + r) * E_ + v + 128];
    }
    __syncthreads();

    ull acc[4];
    #pragma unroll
    for (int r = 0; r < 4; ++r) acc[r] = pack2(0.f, 0.f);

    const ull* wop = (const ull*)g_Wop;
    #pragma unroll 4
    for (int ep = 0; ep < E_ / 2; ++ep) {
        ull wp = wop[ep * V_ + v];
        #pragma unroll
        for (int r = 0; r < 4; ++r)
            acc[r] = ffma2(((const ull*)av4[r])[ep], wp, acc[r]);
    }

    float lg[4], wb = Wob[v];
    #pragma unroll
    for (int r = 0; r < 4; ++r) {
        float lo, hi; unpack2(acc[r], lo, hi);
        lg[r] = lo + hi + wb;
    }

    float wm[4];
    #pragma unroll
    for (int r = 0; r < 4; ++r) {
        wm[r] = lg[r];
        #pragma unroll
        for (int off = 16; off; off >>= 1)
            wm[r] = fmaxf(wm[r], __shfl_xor_sync(0xffffffffu, wm[r], off));
    }
    if (lane == 0) {
        #pragma unroll
        for (int r = 0; r < 4; ++r) redm[r][wid] = wm[r];
    }
    __syncthreads();
    float bm[4];
    #pragma unroll
    for (int r = 0; r < 4; ++r)
        bm[r] = fmaxf(fmaxf(redm[r][0], redm[r][1]), fmaxf(redm[r][2], redm[r][3]));

    float ws[4];
    #pragma unroll
    for (int r = 0; r < 4; ++r) {
        ws[r] = expf(lg[r] - bm[r]);
        #pragma unroll
        for (int off = 16; off; off >>= 1)
            ws[r] += __shfl_xor_sync(0xffffffffu, ws[r], off);
    }
    if (lane == 0) {
        #pragma unroll
        for (int r = 0; r < 4; ++r) reds[r][wid] = ws[r];
    }
    __syncthreads();

    #pragma unroll
    for (int r = 0; r < 4; ++r) {
        float bs = reds[r][0] + reds[r][1] + reds[r][2] + reds[r][3];
        out[(row0 + r) * V_ + v] = lg[r] - bm[r] - logf(bs);
    }
}

// ---------------------------------------------------------------------------
// kernel_launch
// ---------------------------------------------------------------------------
extern "C" void kernel_launch(void* const* d_in, const int* in_sizes, int n_in,
                              void* d_out, int out_size) {
    int li = 2;
    for (int i = 0; i < n_in; ++i)
        if (in_sizes[i] == 1024) { li = i; break; }

    const float *enc, *dec, *emb, *cw, *cb, *Ww, *Wb, *Wo, *Wob;
    const int* labels;
    if (li == 2) {
        enc = (const float*)d_in[0]; dec = (const float*)d_in[1];
        labels = (const int*)d_in[2];
        emb = (const float*)d_in[3]; cw  = (const float*)d_in[4];
        cb  = (const float*)d_in[5]; Ww  = (const float*)d_in[6];
        Wb  = (const float*)d_in[7]; Wo  = (const float*)d_in[8];
        Wob = (const float*)d_in[9];
    } else {
        enc = (const float*)d_in[0]; dec = (const float*)d_in[1];
        emb = (const float*)d_in[2]; cw  = (const float*)d_in[3];
        cb  = (const float*)d_in[4]; Ww  = (const float*)d_in[5];
        Wb  = (const float*)d_in[6]; Wo  = (const float*)d_in[7];
        Wob = (const float*)d_in[8];
        labels = (const int*)d_in[9];
    }
    float* out = (float*)d_out;

    k_embed   <<<BT_, 256>>>(labels, emb);
    k_residual<<<(B_ * HW_ * E_) / 4 / 256, 256>>>(enc, dec);
    k_prep    <<<E_ + V_ + 3 * E_ + 1, 256>>>(Ww, Wo, cw, cb);
    k_transpose<<<dim3(HW_ / 32, E_ / 32, B_), dim3(32, 8)>>>(dec);

    for (int l = 0; l < NBLK_; ++l) {
        k_conv2<<<128, 256>>>();
        k_hW   <<<128, 256>>>(Wb);
        k_attn <<<128, 256>>>();
    }

    k_logits<<<BT_ / 4, 128>>>(Wob, out);
}